// round 1
// baseline (speedup 1.0000x reference)
#include <cuda_runtime.h>
#include <math.h>

// Problem constants
#define BATCH   8
#define CDIM    256
#define HDIM    56
#define WDIM    56
#define HW      3136            // 56*56
#define L_TOTAL 25088           // 8*3136
#define DDIM    2304            // 256*9

// Scratch (device globals — no runtime allocation)
__device__ __align__(128) float g_t [L_TOTAL * (size_t)DDIM];  // unfold(x): 231 MB
__device__ __align__(128) float g_h1[L_TOTAL * (size_t)CDIM];  // relu(t@W1+b1): 25.7 MB
__device__ __align__(128) float g_p [L_TOTAL * (size_t)DDIM];  // t * sigmoid(h1@W2+b2): 231 MB

// ---------------------------------------------------------------------------
// K0: unfold 3x3 pad=1, channel order d = c*9 + ki*3 + kj
// ---------------------------------------------------------------------------
__global__ __launch_bounds__(256) void unfold_kernel(const float* __restrict__ x) {
    int idx = blockIdx.x * 256 + threadIdx.x;
    if (idx >= L_TOTAL * DDIM) return;
    int d = idx % DDIM;
    int l = idx / DDIM;
    int b = l / HW;
    int p = l % HW;
    int h = p / WDIM;
    int w = p % WDIM;
    int c = d / 9;
    int r = d % 9;
    int ki = r / 3, kj = r % 3;
    int hh = h + ki - 1, ww = w + kj - 1;
    float v = 0.f;
    if (hh >= 0 && hh < HDIM && ww >= 0 && ww < WDIM)
        v = x[((b * CDIM + c) * HDIM + hh) * WDIM + ww];
    g_t[idx] = v;
}

// ---------------------------------------------------------------------------
// Tiled GEMM: C[M,N] = epilogue(A[M,K] @ B[K,N] + bias[N])
// BM=128, BN=128, BK=16, 256 threads, 8x8 outputs/thread (2x2 blocks of 4x4)
// MODE 1: relu           MODE 2: sigmoid * taux   MODE 3: plain bias
// M % 128 == 0, N % 128 == 0, K % 16 == 0 (all hold here)
// ---------------------------------------------------------------------------
template<int MODE>
__global__ __launch_bounds__(256) void gemm_kernel(
    const float* __restrict__ A, const float* __restrict__ Bm,
    const float* __restrict__ bias, const float* __restrict__ taux,
    float* __restrict__ Cm, int M, int N, int Kd)
{
    __shared__ float As[16][128];
    __shared__ float Bs[16][128];

    const int tid = threadIdx.x;
    const int m0  = blockIdx.y * 128;
    const int n0  = blockIdx.x * 128;
    const int ty  = tid >> 4;      // 0..15
    const int tx  = tid & 15;      // 0..15

    float acc[8][8];
    #pragma unroll
    for (int i = 0; i < 8; i++)
        #pragma unroll
        for (int j = 0; j < 8; j++) acc[i][j] = 0.f;

    for (int k0 = 0; k0 < Kd; k0 += 16) {
        // Load A tile (128 rows x 16 k), transposed into As[k][m]
        #pragma unroll
        for (int i = 0; i < 2; i++) {
            int idx = tid + i * 256;          // 0..511 float4 slots
            int row = idx >> 2;               // 0..127
            int c4  = idx & 3;                // 0..3
            float4 v = *(const float4*)&A[(size_t)(m0 + row) * Kd + k0 + c4 * 4];
            As[c4 * 4 + 0][row] = v.x;
            As[c4 * 4 + 1][row] = v.y;
            As[c4 * 4 + 2][row] = v.z;
            As[c4 * 4 + 3][row] = v.w;
        }
        // Load B tile (16 k x 128 n)
        #pragma unroll
        for (int i = 0; i < 2; i++) {
            int idx = tid + i * 256;
            int k   = idx >> 5;               // 0..15
            int n4  = idx & 31;               // 0..31
            *(float4*)&Bs[k][n4 * 4] =
                *(const float4*)&Bm[(size_t)(k0 + k) * N + n0 + n4 * 4];
        }
        __syncthreads();

        #pragma unroll
        for (int k = 0; k < 16; k++) {
            float4 a0 = *(const float4*)&As[k][ty * 4];
            float4 a1 = *(const float4*)&As[k][ty * 4 + 64];
            float4 b0 = *(const float4*)&Bs[k][tx * 4];
            float4 b1 = *(const float4*)&Bs[k][tx * 4 + 64];
            float av[8] = {a0.x, a0.y, a0.z, a0.w, a1.x, a1.y, a1.z, a1.w};
            float bv[8] = {b0.x, b0.y, b0.z, b0.w, b1.x, b1.y, b1.z, b1.w};
            #pragma unroll
            for (int i = 0; i < 8; i++)
                #pragma unroll
                for (int j = 0; j < 8; j++)
                    acc[i][j] = fmaf(av[i], bv[j], acc[i][j]);
        }
        __syncthreads();
    }

    // Epilogue
    #pragma unroll
    for (int ii = 0; ii < 8; ii++) {
        int m = m0 + ((ii >> 2) << 6) + ty * 4 + (ii & 3);
        #pragma unroll
        for (int jh = 0; jh < 2; jh++) {
            int n = n0 + (jh << 6) + tx * 4;
            float4 bv = *(const float4*)&bias[n];
            float4 v;
            v.x = acc[ii][jh * 4 + 0] + bv.x;
            v.y = acc[ii][jh * 4 + 1] + bv.y;
            v.z = acc[ii][jh * 4 + 2] + bv.z;
            v.w = acc[ii][jh * 4 + 3] + bv.w;
            if (MODE == 1) {
                v.x = fmaxf(v.x, 0.f); v.y = fmaxf(v.y, 0.f);
                v.z = fmaxf(v.z, 0.f); v.w = fmaxf(v.w, 0.f);
            } else if (MODE == 2) {
                float4 tv = *(const float4*)&taux[(size_t)m * N + n];
                v.x = tv.x / (1.f + __expf(-v.x));
                v.y = tv.y / (1.f + __expf(-v.y));
                v.z = tv.z / (1.f + __expf(-v.z));
                v.w = tv.w / (1.f + __expf(-v.w));
            }
            *(float4*)&Cm[(size_t)m * N + n] = v;
        }
    }
}

// ---------------------------------------------------------------------------
extern "C" void kernel_launch(void* const* d_in, const int* in_sizes, int n_in,
                              void* d_out, int out_size)
{
    const float* x  = (const float*)d_in[0];
    const float* W1 = (const float*)d_in[1];
    const float* b1 = (const float*)d_in[2];
    const float* W2 = (const float*)d_in[3];
    const float* b2 = (const float*)d_in[4];
    const float* W3 = (const float*)d_in[5];
    const float* b3 = (const float*)d_in[6];
    float* out = (float*)d_out;

    float *pt, *ph1, *pp;
    cudaGetSymbolAddress((void**)&pt,  g_t);
    cudaGetSymbolAddress((void**)&ph1, g_h1);
    cudaGetSymbolAddress((void**)&pp,  g_p);

    // K0: unfold
    {
        int total = L_TOTAL * DDIM;
        unfold_kernel<<<(total + 255) / 256, 256>>>(x);
    }
    // K1: h1 = relu(t @ W1 + b1)     [25088 x 256], K=2304
    gemm_kernel<1><<<dim3(CDIM / 128, L_TOTAL / 128), 256>>>(
        pt, W1, b1, nullptr, ph1, L_TOTAL, CDIM, DDIM);
    // K2: p = t * sigmoid(h1 @ W2 + b2)   [25088 x 2304], K=256
    gemm_kernel<2><<<dim3(DDIM / 128, L_TOTAL / 128), 256>>>(
        ph1, W2, b2, pt, pp, L_TOTAL, DDIM, CDIM);
    // K3: out = p @ W3 + b3          [25088 x 256], K=2304
    gemm_kernel<3><<<dim3(CDIM / 128, L_TOTAL / 128), 256>>>(
        pp, W3, b3, nullptr, out, L_TOTAL, CDIM, DDIM);
}

// round 5
// speedup vs baseline: 1.6086x; 1.6086x over previous
#include <cuda_runtime.h>
#include <cuda_bf16.h>
#include <stdint.h>
#include <math.h>

// ---------------- problem constants ----------------
#define CDIM    256
#define HDIM    56
#define WDIM    56
#define HW      3136
#define L_TOTAL 25088
#define DDIM    2304

// ---------------- scratch (packed bf16 hi/lo pairs as u32) ----------------
__device__ __align__(128) unsigned int g_t  [(size_t)L_TOTAL * DDIM];
__device__ __align__(128) unsigned int g_h1 [(size_t)L_TOTAL * CDIM];
__device__ __align__(128) unsigned int g_p  [(size_t)L_TOTAL * DDIM];
__device__ __align__(128) unsigned int g_w1t[(size_t)CDIM * DDIM];
__device__ __align__(128) unsigned int g_w2t[(size_t)DDIM * CDIM];
__device__ __align__(128) unsigned int g_w3t[(size_t)CDIM * DDIM];

// ---------------- helpers ----------------
__device__ __forceinline__ uint32_t smem_u32(const void* p) {
    uint32_t a;
    asm("{ .reg .u64 t; cvta.to.shared.u64 t, %1; cvt.u32.u64 %0, t; }" : "=r"(a) : "l"(p));
    return a;
}
__device__ __forceinline__ void ldm_x4(uint32_t* r, uint32_t addr) {
    asm volatile("ldmatrix.sync.aligned.m8n8.x4.shared.b16 {%0,%1,%2,%3}, [%4];"
        : "=r"(r[0]), "=r"(r[1]), "=r"(r[2]), "=r"(r[3]) : "r"(addr));
}
__device__ __forceinline__ void mma16816(float* d, const uint32_t* a, uint32_t b0, uint32_t b1) {
    asm volatile("mma.sync.aligned.m16n8k16.row.col.f32.bf16.bf16.f32 "
        "{%0,%1,%2,%3}, {%4,%5,%6,%7}, {%8,%9}, {%0,%1,%2,%3};"
        : "+f"(d[0]), "+f"(d[1]), "+f"(d[2]), "+f"(d[3])
        : "r"(a[0]), "r"(a[1]), "r"(a[2]), "r"(a[3]), "r"(b0), "r"(b1));
}

// pack fp32 -> (bf16 hi in low16, bf16 lo in high16)
__device__ __forceinline__ unsigned int split_pack(float v) {
    __nv_bfloat16 hi = __float2bfloat16(v);
    __nv_bfloat16 lo = __float2bfloat16(v - __bfloat162float(hi));
    __nv_bfloat162 pr; pr.x = hi; pr.y = lo;
    unsigned int u; memcpy(&u, &pr, 4);
    return u;
}
__device__ __forceinline__ float unsplit(unsigned int u) {
    __nv_bfloat162 pr; memcpy(&pr, &u, 4);
    return __bfloat162float(pr.x) + __bfloat162float(pr.y);
}

// ---------------- K0: unfold + split ----------------
__global__ __launch_bounds__(256) void unfold_pack(const float* __restrict__ x, unsigned int* __restrict__ tpk) {
    long long idx = (long long)blockIdx.x * 256 + threadIdx.x;
    if (idx >= (long long)L_TOTAL * DDIM) return;
    int d = (int)(idx % DDIM);
    int l = (int)(idx / DDIM);
    int b = l / HW, p = l % HW;
    int h = p / WDIM, w = p % WDIM;
    int c = d / 9, r = d % 9;
    int hh = h + r / 3 - 1, ww = w + r % 3 - 1;
    float v = 0.f;
    if (hh >= 0 && hh < HDIM && ww >= 0 && ww < WDIM)
        v = x[((b * CDIM + c) * HDIM + hh) * WDIM + ww];
    tpk[idx] = split_pack(v);
}

// ---------------- weight transpose + split: W[K,N] -> out[N,K] packed ----------------
__global__ __launch_bounds__(256) void wtrans_pack(const float* __restrict__ W, unsigned int* __restrict__ out, int K, int N) {
    int t = blockIdx.x * 256 + threadIdx.x;
    if (t >= K * N) return;
    int k = t % K, n = t / K;
    out[(size_t)n * K + k] = split_pack(W[(size_t)k * N + n]);
}

// ---------------- compensated bf16 mma.sync GEMM ----------------
// C[M,N] = epi(A[M,K] @ Bt^T + bias); A [M,K], Bt [N,K], both packed (hi,lo) bf16 in u32.
// BM=128, BN=128, BK=32, 256 threads, warp grid 4(m) x 2(n), warp tile 32x64.
// 3 MMAs per fragment pair: hi*hi + hi*lo + lo*hi (Markidis compensation).
// MODE 1: relu->packed   MODE 2: sigmoid*aux->packed   MODE 3: fp32 out
#define PITCH 80                 // bytes per 32-bf16 row (64B data + 16B pad)
#define TILE_B (128 * PITCH)     // 10240 bytes per (hi or lo) tile

template<int MODE>
__global__ __launch_bounds__(256) void gemm_mma(
    const unsigned int* __restrict__ Ap, const unsigned int* __restrict__ Bp,
    const float* __restrict__ bias, const unsigned int* __restrict__ aux,
    void* __restrict__ outp, int M, int N, int Kd)
{
    __shared__ __align__(16) char smem[4 * TILE_B];
    const uint32_t sb = smem_u32(smem);

    const int tid  = threadIdx.x;
    const int lane = tid & 31;
    const int wid  = tid >> 5;
    const int warp_m = wid & 3;      // 0..3  (32-row slabs)
    const int warp_n = wid >> 2;     // 0..1  (64-col slabs)
    const int m0 = blockIdx.y * 128;
    const int n0 = blockIdx.x * 128;

    const int ldrow0 = tid >> 3;     // 0..31
    const int sc4    = tid & 7;      // 0..7 (16B chunk within 64B k-row)

    uint4 stA[4], stB[4];
    float acc[2][8][4];
    #pragma unroll
    for (int a = 0; a < 2; a++)
        #pragma unroll
        for (int b = 0; b < 8; b++)
            #pragma unroll
            for (int c = 0; c < 4; c++) acc[a][b][c] = 0.f;

    // ldmatrix lane addressing (x4: 4 8x8 matrices)
    const int grp = lane >> 3, r8 = lane & 7;
    const int rowoff = ((grp & 1) << 3) + r8;     // 0..15
    const int coloff = (grp >> 1) << 4;           // 0 or 16 bytes
    const uint32_t aHiB = sb + 0 * TILE_B + (warp_m * 32 + rowoff) * PITCH + coloff;
    const uint32_t aLoB = sb + 1 * TILE_B + (warp_m * 32 + rowoff) * PITCH + coloff;
    const uint32_t bHiB = sb + 2 * TILE_B + (warp_n * 64 + rowoff) * PITCH + coloff;
    const uint32_t bLoB = sb + 3 * TILE_B + (warp_n * 64 + rowoff) * PITCH + coloff;

    // initial global fetch (k0 = 0)
    #pragma unroll
    for (int i = 0; i < 4; i++) {
        int row = ldrow0 + i * 32;
        stA[i] = *(const uint4*)(Ap + (size_t)(m0 + row) * Kd + sc4 * 4);
        stB[i] = *(const uint4*)(Bp + (size_t)(n0 + row) * Kd + sc4 * 4);
    }

    for (int k0 = 0; k0 < Kd; k0 += 32) {
        // store staged regs -> smem (de-interleave hi/lo)
        #pragma unroll
        for (int i = 0; i < 4; i++) {
            int row = ldrow0 + i * 32;
            uint32_t so = row * PITCH + sc4 * 8;
            uint2 h, l;
            h.x = __byte_perm(stA[i].x, stA[i].y, 0x5410); h.y = __byte_perm(stA[i].z, stA[i].w, 0x5410);
            l.x = __byte_perm(stA[i].x, stA[i].y, 0x7632); l.y = __byte_perm(stA[i].z, stA[i].w, 0x7632);
            *(uint2*)(smem + so)              = h;
            *(uint2*)(smem + TILE_B + so)     = l;
            h.x = __byte_perm(stB[i].x, stB[i].y, 0x5410); h.y = __byte_perm(stB[i].z, stB[i].w, 0x5410);
            l.x = __byte_perm(stB[i].x, stB[i].y, 0x7632); l.y = __byte_perm(stB[i].z, stB[i].w, 0x7632);
            *(uint2*)(smem + 2 * TILE_B + so) = h;
            *(uint2*)(smem + 3 * TILE_B + so) = l;
        }
        __syncthreads();

        if (k0 + 32 < Kd) {
            int kn = k0 + 32;
            #pragma unroll
            for (int i = 0; i < 4; i++) {
                int row = ldrow0 + i * 32;
                stA[i] = *(const uint4*)(Ap + (size_t)(m0 + row) * Kd + kn + sc4 * 4);
                stB[i] = *(const uint4*)(Bp + (size_t)(n0 + row) * Kd + kn + sc4 * 4);
            }
        }

        #pragma unroll
        for (int ks = 0; ks < 2; ks++) {
            uint32_t ah[2][4], al[2][4], bh[4][4], bl[4][4];
            #pragma unroll
            for (int tm = 0; tm < 2; tm++) {
                ldm_x4(ah[tm], aHiB + tm * 16 * PITCH + ks * 32);
                ldm_x4(al[tm], aLoB + tm * 16 * PITCH + ks * 32);
            }
            #pragma unroll
            for (int p = 0; p < 4; p++) {
                ldm_x4(bh[p], bHiB + p * 16 * PITCH + ks * 32);
                ldm_x4(bl[p], bLoB + p * 16 * PITCH + ks * 32);
            }
            #pragma unroll
            for (int tm = 0; tm < 2; tm++)
                #pragma unroll
                for (int tn = 0; tn < 8; tn++) {
                    int p = tn >> 1, o = tn & 1;
                    mma16816(acc[tm][tn], ah[tm], bh[p][o], bh[p][2 + o]);
                    mma16816(acc[tm][tn], ah[tm], bl[p][o], bl[p][2 + o]);
                    mma16816(acc[tm][tn], al[tm], bh[p][o], bh[p][2 + o]);
                }
        }
        __syncthreads();
    }

    // ---------------- epilogue ----------------
    const int qr = lane >> 2;          // row within m8
    const int qc = (lane & 3) * 2;     // col pair within n8
    #pragma unroll
    for (int tm = 0; tm < 2; tm++) {
        int mb = m0 + warp_m * 32 + tm * 16;
        #pragma unroll
        for (int tn = 0; tn < 8; tn++) {
            int n = n0 + warp_n * 64 + tn * 8 + qc;
            float bx = bias[n], by = bias[n + 1];
            #pragma unroll
            for (int half = 0; half < 2; half++) {
                int m = mb + qr + half * 8;
                float vx = acc[tm][tn][half * 2 + 0] + bx;
                float vy = acc[tm][tn][half * 2 + 1] + by;
                size_t o = (size_t)m * N + n;
                if (MODE == 1) {
                    uint2 w;
                    w.x = split_pack(fmaxf(vx, 0.f));
                    w.y = split_pack(fmaxf(vy, 0.f));
                    *(uint2*)((unsigned int*)outp + o) = w;
                } else if (MODE == 2) {
                    float sx = 1.f / (1.f + __expf(-vx));
                    float sy = 1.f / (1.f + __expf(-vy));
                    uint2 tv = *(const uint2*)(aux + o);
                    uint2 w;
                    w.x = split_pack(unsplit(tv.x) * sx);
                    w.y = split_pack(unsplit(tv.y) * sy);
                    *(uint2*)((unsigned int*)outp + o) = w;
                } else {
                    float2 w; w.x = vx; w.y = vy;
                    *(float2*)((float*)outp + o) = w;
                }
            }
        }
    }
}

// ---------------- host launch ----------------
extern "C" void kernel_launch(void* const* d_in, const int* in_sizes, int n_in,
                              void* d_out, int out_size)
{
    const float* x  = (const float*)d_in[0];
    const float* W1 = (const float*)d_in[1];
    const float* b1 = (const float*)d_in[2];
    const float* W2 = (const float*)d_in[3];
    const float* b2 = (const float*)d_in[4];
    const float* W3 = (const float*)d_in[5];
    const float* b3 = (const float*)d_in[6];
    float* out = (float*)d_out;

    unsigned int *pt, *ph1, *pp, *pw1, *pw2, *pw3;
    cudaGetSymbolAddress((void**)&pt,  g_t);
    cudaGetSymbolAddress((void**)&ph1, g_h1);
    cudaGetSymbolAddress((void**)&pp,  g_p);
    cudaGetSymbolAddress((void**)&pw1, g_w1t);
    cudaGetSymbolAddress((void**)&pw2, g_w2t);
    cudaGetSymbolAddress((void**)&pw3, g_w3t);

    long long tot = (long long)L_TOTAL * DDIM;
    unfold_pack<<<(unsigned)((tot + 255) / 256), 256>>>(x, pt);
    wtrans_pack<<<(DDIM * CDIM + 255) / 256, 256>>>(W1, pw1, DDIM, CDIM);
    wtrans_pack<<<(CDIM * DDIM + 255) / 256, 256>>>(W2, pw2, CDIM, DDIM);
    wtrans_pack<<<(DDIM * CDIM + 255) / 256, 256>>>(W3, pw3, DDIM, CDIM);

    // K1: h1 = relu(t @ W1 + b1)        [25088 x 256],  K=2304
    gemm_mma<1><<<dim3(CDIM / 128, L_TOTAL / 128), 256>>>(
        pt, pw1, b1, nullptr, ph1, L_TOTAL, CDIM, DDIM);
    // K2: p = t * sigmoid(h1 @ W2 + b2) [25088 x 2304], K=256
    gemm_mma<2><<<dim3(DDIM / 128, L_TOTAL / 128), 256>>>(
        ph1, pw2, b2, pt, pp, L_TOTAL, DDIM, CDIM);
    // K3: out = p @ W3 + b3             [25088 x 256],  K=2304
    gemm_mma<3><<<dim3(CDIM / 128, L_TOTAL / 128), 256>>>(
        pp, pw3, b3, nullptr, out, L_TOTAL, CDIM, DDIM);
}

// round 6
// speedup vs baseline: 2.2733x; 1.4132x over previous
#include <cuda_runtime.h>
#include <cuda_bf16.h>
#include <stdint.h>
#include <math.h>

// ---------------- problem constants ----------------
#define CDIM    256
#define HDIM    56
#define WDIM    56
#define HW      3136
#define L_TOTAL 25088
#define DDIM    2304

// ---------------- scratch: separate hi/lo bf16 planes ----------------
__device__ __align__(128) __nv_bfloat16 g_t_hi [(size_t)L_TOTAL * DDIM];
__device__ __align__(128) __nv_bfloat16 g_t_lo [(size_t)L_TOTAL * DDIM];
__device__ __align__(128) __nv_bfloat16 g_h_hi [(size_t)L_TOTAL * CDIM];
__device__ __align__(128) __nv_bfloat16 g_h_lo [(size_t)L_TOTAL * CDIM];
__device__ __align__(128) __nv_bfloat16 g_p_hi [(size_t)L_TOTAL * DDIM];
__device__ __align__(128) __nv_bfloat16 g_p_lo [(size_t)L_TOTAL * DDIM];
__device__ __align__(128) __nv_bfloat16 g_w1_hi[(size_t)CDIM * DDIM];
__device__ __align__(128) __nv_bfloat16 g_w1_lo[(size_t)CDIM * DDIM];
__device__ __align__(128) __nv_bfloat16 g_w2_hi[(size_t)DDIM * CDIM];
__device__ __align__(128) __nv_bfloat16 g_w2_lo[(size_t)DDIM * CDIM];
__device__ __align__(128) __nv_bfloat16 g_w3_hi[(size_t)CDIM * DDIM];
__device__ __align__(128) __nv_bfloat16 g_w3_lo[(size_t)CDIM * DDIM];

// ---------------- helpers ----------------
__device__ __forceinline__ uint32_t smem_u32(const void* p) {
    uint32_t a;
    asm("{ .reg .u64 t; cvta.to.shared.u64 t, %1; cvt.u32.u64 %0, t; }" : "=r"(a) : "l"(p));
    return a;
}
__device__ __forceinline__ void ldm_x4(uint32_t* r, uint32_t addr) {
    asm volatile("ldmatrix.sync.aligned.m8n8.x4.shared.b16 {%0,%1,%2,%3}, [%4];"
        : "=r"(r[0]), "=r"(r[1]), "=r"(r[2]), "=r"(r[3]) : "r"(addr));
}
__device__ __forceinline__ void mma16816(float* d, const uint32_t* a, uint32_t b0, uint32_t b1) {
    asm volatile("mma.sync.aligned.m16n8k16.row.col.f32.bf16.bf16.f32 "
        "{%0,%1,%2,%3}, {%4,%5,%6,%7}, {%8,%9}, {%0,%1,%2,%3};"
        : "+f"(d[0]), "+f"(d[1]), "+f"(d[2]), "+f"(d[3])
        : "r"(a[0]), "r"(a[1]), "r"(a[2]), "r"(a[3]), "r"(b0), "r"(b1));
}
__device__ __forceinline__ void cp_async16(uint32_t dst, const void* src) {
    asm volatile("cp.async.cg.shared.global [%0], [%1], 16;" :: "r"(dst), "l"(src));
}
#define CP_COMMIT() asm volatile("cp.async.commit_group;" ::: "memory")
#define CP_WAIT2()  asm volatile("cp.async.wait_group 2;" ::: "memory")

__device__ __forceinline__ void split_to(float v, __nv_bfloat16& h, __nv_bfloat16& l) {
    h = __float2bfloat16(v);
    l = __float2bfloat16(v - __bfloat162float(h));
}

// ---------------- K0: unfold -> hi/lo planes (paired stores) ----------------
__global__ __launch_bounds__(256) void unfold_pack2(const float* __restrict__ x,
    __nv_bfloat16* __restrict__ thi, __nv_bfloat16* __restrict__ tlo)
{
    long long pidx = (long long)blockIdx.x * 256 + threadIdx.x;
    const long long NP = (long long)L_TOTAL * (DDIM / 2);
    if (pidx >= NP) return;
    int dp = (int)(pidx % (DDIM / 2));
    int l  = (int)(pidx / (DDIM / 2));
    int d0 = dp * 2;
    int b = l / HW, p = l % HW;
    int h = p / WDIM, w = p % WDIM;
    float v[2];
    #pragma unroll
    for (int j = 0; j < 2; j++) {
        int d = d0 + j;
        int c = d / 9, r = d % 9;
        int hh = h + r / 3 - 1, ww = w + r % 3 - 1;
        float vv = 0.f;
        if (hh >= 0 && hh < HDIM && ww >= 0 && ww < WDIM)
            vv = x[((b * CDIM + c) * HDIM + hh) * WDIM + ww];
        v[j] = vv;
    }
    __nv_bfloat162 h2, l2;
    split_to(v[0], h2.x, l2.x);
    split_to(v[1], h2.y, l2.y);
    size_t o = (size_t)l * DDIM + d0;
    *(__nv_bfloat162*)(thi + o) = h2;
    *(__nv_bfloat162*)(tlo + o) = l2;
}

// ---------------- weight transpose: W[K,N] -> planes[N,K] ----------------
__global__ __launch_bounds__(256) void wtrans_pack2(const float* __restrict__ W,
    __nv_bfloat16* __restrict__ ohi, __nv_bfloat16* __restrict__ olo, int K, int N)
{
    int t = blockIdx.x * 256 + threadIdx.x;
    int NP = N * (K / 2);
    if (t >= NP) return;
    int kp = t % (K / 2), n = t / (K / 2);
    int k0 = kp * 2;
    float v0 = W[(size_t)k0 * N + n];
    float v1 = W[(size_t)(k0 + 1) * N + n];
    __nv_bfloat162 h2, l2;
    split_to(v0, h2.x, l2.x);
    split_to(v1, h2.y, l2.y);
    size_t o = (size_t)n * K + k0;
    *(__nv_bfloat162*)(ohi + o) = h2;
    *(__nv_bfloat162*)(olo + o) = l2;
}

// ---------------- pipelined compensated bf16 mma.sync GEMM ----------------
// C[M,N] = epi(A @ Bt^T + bias); A planes [M,K], Bt planes [N,K].
// BM=128 BN=128 BK=32, 256 threads, 3-stage cp.async pipeline.
// Markidis: hi*hi + hi*lo + lo*hi.
// MODE 1: relu -> planes   MODE 2: sigmoid*X -> planes   MODE 3: fp32 out
#define STAGE_B 32768            // 4 planes x (128 rows x 64B)
#define NSTAGE  3

template<int MODE>
__global__ __launch_bounds__(256) void gemm_mma(
    const __nv_bfloat16* __restrict__ Ahi, const __nv_bfloat16* __restrict__ Alo,
    const __nv_bfloat16* __restrict__ Bhi, const __nv_bfloat16* __restrict__ Blo,
    const float* __restrict__ bias,
    const __nv_bfloat16* __restrict__ Xhi, const __nv_bfloat16* __restrict__ Xlo,
    __nv_bfloat16* __restrict__ Ohi, __nv_bfloat16* __restrict__ Olo,
    float* __restrict__ Of, int M, int N, int Kd)
{
    extern __shared__ __align__(128) char smem[];
    const uint32_t sb = smem_u32(smem);

    const int tid  = threadIdx.x;
    const int lane = tid & 31;
    const int wid  = tid >> 5;
    const int warp_m = wid & 3;
    const int warp_n = wid >> 2;
    const int m0 = blockIdx.y * 128;
    const int n0 = blockIdx.x * 128;

    // cp.async assignment: 8 chunks of 16B per thread per stage
    const int lr = tid >> 2;          // 0..63 base row
    const int lc = tid & 3;           // chunk 0..3

    float acc[2][8][4];
    #pragma unroll
    for (int a = 0; a < 2; a++)
        #pragma unroll
        for (int b = 0; b < 8; b++)
            #pragma unroll
            for (int c = 0; c < 4; c++) acc[a][b][c] = 0.f;

    // ldmatrix per-lane addressing
    const int grp = lane >> 3, r8 = lane & 7;
    const int rowoff = ((grp & 1) << 3) + r8;     // 0..15
    const int cg = grp >> 1;                      // 16B chunk within 32B k-half
    int offA[2], swA[2], offB[4], swB[4];
    #pragma unroll
    for (int tm = 0; tm < 2; tm++) {
        int r = warp_m * 32 + tm * 16 + rowoff;
        offA[tm] = r * 64; swA[tm] = (r >> 1) & 3;
    }
    #pragma unroll
    for (int p = 0; p < 4; p++) {
        int r = warp_n * 64 + p * 16 + rowoff;
        offB[p] = r * 64; swB[p] = (r >> 1) & 3;
    }

    const int NIT = Kd >> 5;

    // stage loader
    auto load_stage = [&](int st, int k0) {
        uint32_t stb = sb + st * STAGE_B;
        #pragma unroll
        for (int i = 0; i < 8; i++) {
            int plane = i >> 1;
            int r = ((i & 1) << 6) + lr;
            uint32_t dst = stb + plane * 8192 + r * 64 + ((lc ^ ((r >> 1) & 3)) << 4);
            const char* src;
            if (plane == 0)      src = (const char*)(Ahi + (size_t)(m0 + r) * Kd + k0 + lc * 8);
            else if (plane == 1) src = (const char*)(Alo + (size_t)(m0 + r) * Kd + k0 + lc * 8);
            else if (plane == 2) src = (const char*)(Bhi + (size_t)(n0 + r) * Kd + k0 + lc * 8);
            else                 src = (const char*)(Blo + (size_t)(n0 + r) * Kd + k0 + lc * 8);
            cp_async16(dst, src);
        }
    };

    #pragma unroll
    for (int s = 0; s < NSTAGE; s++) {
        load_stage(s, s * 32);
        CP_COMMIT();
    }

    for (int it = 0; it < NIT; it++) {
        CP_WAIT2();
        __syncthreads();
        const int st = it % NSTAGE;
        const uint32_t stb = sb + st * STAGE_B;

        #pragma unroll
        for (int ks = 0; ks < 2; ks++) {
            uint32_t ah[2][4], al[2][4], bh[4][4], bl[4][4];
            #pragma unroll
            for (int tm = 0; tm < 2; tm++) {
                uint32_t colA = (uint32_t)((((ks << 1) | cg) ^ swA[tm]) << 4);
                ldm_x4(ah[tm], stb + 0 * 8192 + offA[tm] + colA);
                ldm_x4(al[tm], stb + 1 * 8192 + offA[tm] + colA);
            }
            #pragma unroll
            for (int p = 0; p < 4; p++) {
                uint32_t colB = (uint32_t)((((ks << 1) | cg) ^ swB[p]) << 4);
                ldm_x4(bh[p], stb + 2 * 8192 + offB[p] + colB);
                ldm_x4(bl[p], stb + 3 * 8192 + offB[p] + colB);
            }
            #pragma unroll
            for (int tm = 0; tm < 2; tm++)
                #pragma unroll
                for (int tn = 0; tn < 8; tn++) {
                    int p = tn >> 1, o = tn & 1;
                    mma16816(acc[tm][tn], ah[tm], bh[p][o], bh[p][2 + o]);
                    mma16816(acc[tm][tn], ah[tm], bl[p][o], bl[p][2 + o]);
                    mma16816(acc[tm][tn], al[tm], bh[p][o], bh[p][2 + o]);
                }
        }
        __syncthreads();

        int nxt = it + NSTAGE;
        if (nxt < NIT) load_stage(st, nxt * 32);
        CP_COMMIT();
    }

    // ---------------- epilogue ----------------
    const int qr = lane >> 2;
    const int qc = (lane & 3) * 2;
    #pragma unroll
    for (int tm = 0; tm < 2; tm++) {
        int mb = m0 + warp_m * 32 + tm * 16;
        #pragma unroll
        for (int tn = 0; tn < 8; tn++) {
            int n = n0 + warp_n * 64 + tn * 8 + qc;
            float bx = bias[n], by = bias[n + 1];
            #pragma unroll
            for (int half = 0; half < 2; half++) {
                int m = mb + qr + half * 8;
                float vx = acc[tm][tn][half * 2 + 0] + bx;
                float vy = acc[tm][tn][half * 2 + 1] + by;
                size_t o = (size_t)m * N + n;
                if (MODE == 1) {
                    float r0 = fmaxf(vx, 0.f), r1 = fmaxf(vy, 0.f);
                    __nv_bfloat162 h2, l2;
                    split_to(r0, h2.x, l2.x);
                    split_to(r1, h2.y, l2.y);
                    *(__nv_bfloat162*)(Ohi + o) = h2;
                    *(__nv_bfloat162*)(Olo + o) = l2;
                } else if (MODE == 2) {
                    float sx = 1.f / (1.f + __expf(-vx));
                    float sy = 1.f / (1.f + __expf(-vy));
                    __nv_bfloat162 th2 = *(const __nv_bfloat162*)(Xhi + o);
                    __nv_bfloat162 tl2 = *(const __nv_bfloat162*)(Xlo + o);
                    float tx = __bfloat162float(th2.x) + __bfloat162float(tl2.x);
                    float ty = __bfloat162float(th2.y) + __bfloat162float(tl2.y);
                    float r0 = tx * sx, r1 = ty * sy;
                    __nv_bfloat162 h2, l2;
                    split_to(r0, h2.x, l2.x);
                    split_to(r1, h2.y, l2.y);
                    *(__nv_bfloat162*)(Ohi + o) = h2;
                    *(__nv_bfloat162*)(Olo + o) = l2;
                } else {
                    float2 w; w.x = vx; w.y = vy;
                    *(float2*)(Of + o) = w;
                }
            }
        }
    }
}

#define SMEM_BYTES (NSTAGE * STAGE_B)

// ---------------- host launch ----------------
extern "C" void kernel_launch(void* const* d_in, const int* in_sizes, int n_in,
                              void* d_out, int out_size)
{
    const float* x  = (const float*)d_in[0];
    const float* W1 = (const float*)d_in[1];
    const float* b1 = (const float*)d_in[2];
    const float* W2 = (const float*)d_in[3];
    const float* b2 = (const float*)d_in[4];
    const float* W3 = (const float*)d_in[5];
    const float* b3 = (const float*)d_in[6];
    float* out = (float*)d_out;

    __nv_bfloat16 *thi, *tlo, *hhi, *hlo, *phi, *plo;
    __nv_bfloat16 *w1h, *w1l, *w2h, *w2l, *w3h, *w3l;
    cudaGetSymbolAddress((void**)&thi, g_t_hi);
    cudaGetSymbolAddress((void**)&tlo, g_t_lo);
    cudaGetSymbolAddress((void**)&hhi, g_h_hi);
    cudaGetSymbolAddress((void**)&hlo, g_h_lo);
    cudaGetSymbolAddress((void**)&phi, g_p_hi);
    cudaGetSymbolAddress((void**)&plo, g_p_lo);
    cudaGetSymbolAddress((void**)&w1h, g_w1_hi);
    cudaGetSymbolAddress((void**)&w1l, g_w1_lo);
    cudaGetSymbolAddress((void**)&w2h, g_w2_hi);
    cudaGetSymbolAddress((void**)&w2l, g_w2_lo);
    cudaGetSymbolAddress((void**)&w3h, g_w3_hi);
    cudaGetSymbolAddress((void**)&w3l, g_w3_lo);

    cudaFuncSetAttribute(gemm_mma<1>, cudaFuncAttributeMaxDynamicSharedMemorySize, SMEM_BYTES);
    cudaFuncSetAttribute(gemm_mma<2>, cudaFuncAttributeMaxDynamicSharedMemorySize, SMEM_BYTES);
    cudaFuncSetAttribute(gemm_mma<3>, cudaFuncAttributeMaxDynamicSharedMemorySize, SMEM_BYTES);

    long long np = (long long)L_TOTAL * (DDIM / 2);
    unfold_pack2<<<(unsigned)((np + 255) / 256), 256>>>(x, thi, tlo);
    wtrans_pack2<<<(CDIM * (DDIM / 2) + 255) / 256, 256>>>(W1, w1h, w1l, DDIM, CDIM);
    wtrans_pack2<<<(DDIM * (CDIM / 2) + 255) / 256, 256>>>(W2, w2h, w2l, CDIM, DDIM);
    wtrans_pack2<<<(CDIM * (DDIM / 2) + 255) / 256, 256>>>(W3, w3h, w3l, DDIM, CDIM);

    // K1: h1 = relu(t @ W1 + b1)        [25088 x 256],  K=2304
    gemm_mma<1><<<dim3(CDIM / 128, L_TOTAL / 128), 256, SMEM_BYTES>>>(
        thi, tlo, w1h, w1l, b1, nullptr, nullptr, hhi, hlo, nullptr, L_TOTAL, CDIM, DDIM);
    // K2: p = t * sigmoid(h1 @ W2 + b2) [25088 x 2304], K=256
    gemm_mma<2><<<dim3(DDIM / 128, L_TOTAL / 128), 256, SMEM_BYTES>>>(
        hhi, hlo, w2h, w2l, b2, thi, tlo, phi, plo, nullptr, L_TOTAL, DDIM, CDIM);
    // K3: out = p @ W3 + b3             [25088 x 256],  K=2304
    gemm_mma<3><<<dim3(CDIM / 128, L_TOTAL / 128), 256, SMEM_BYTES>>>(
        phi, plo, w3h, w3l, b3, nullptr, nullptr, nullptr, nullptr, out, L_TOTAL, CDIM, DDIM);
}

// round 7
// speedup vs baseline: 3.3359x; 1.4674x over previous
#include <cuda_runtime.h>
#include <cuda_fp16.h>
#include <stdint.h>
#include <math.h>

// ---------------- problem constants ----------------
#define CDIM    256
#define HDIM    56
#define WDIM    56
#define HW      3136
#define L_TOTAL 25088
#define DDIM    2304

// ---------------- scratch ----------------
// activations: single fp16 plane; weights: hi+lo fp16 planes (N-major [N,K])
__device__ __align__(128) __half g_t [(size_t)L_TOTAL * DDIM];
__device__ __align__(128) __half g_h [(size_t)L_TOTAL * CDIM];
__device__ __align__(128) __half g_p [(size_t)L_TOTAL * DDIM];
__device__ __align__(128) __half g_w1h[(size_t)CDIM * DDIM];
__device__ __align__(128) __half g_w1l[(size_t)CDIM * DDIM];
__device__ __align__(128) __half g_w2h[(size_t)DDIM * CDIM];
__device__ __align__(128) __half g_w2l[(size_t)DDIM * CDIM];
__device__ __align__(128) __half g_w3h[(size_t)CDIM * DDIM];
__device__ __align__(128) __half g_w3l[(size_t)CDIM * DDIM];

// ---------------- helpers ----------------
__device__ __forceinline__ uint32_t smem_u32(const void* p) {
    uint32_t a;
    asm("{ .reg .u64 t; cvta.to.shared.u64 t, %1; cvt.u32.u64 %0, t; }" : "=r"(a) : "l"(p));
    return a;
}
__device__ __forceinline__ void ldm_x4(uint32_t* r, uint32_t addr) {
    asm volatile("ldmatrix.sync.aligned.m8n8.x4.shared.b16 {%0,%1,%2,%3}, [%4];"
        : "=r"(r[0]), "=r"(r[1]), "=r"(r[2]), "=r"(r[3]) : "r"(addr));
}
__device__ __forceinline__ void mma16816(float* d, const uint32_t* a, uint32_t b0, uint32_t b1) {
    asm volatile("mma.sync.aligned.m16n8k16.row.col.f32.f16.f16.f32 "
        "{%0,%1,%2,%3}, {%4,%5,%6,%7}, {%8,%9}, {%0,%1,%2,%3};"
        : "+f"(d[0]), "+f"(d[1]), "+f"(d[2]), "+f"(d[3])
        : "r"(a[0]), "r"(a[1]), "r"(a[2]), "r"(a[3]), "r"(b0), "r"(b1));
}
__device__ __forceinline__ void cp_async16(uint32_t dst, const void* src) {
    asm volatile("cp.async.cg.shared.global [%0], [%1], 16;" :: "r"(dst), "l"(src));
}
#define CP_COMMIT() asm volatile("cp.async.commit_group;" ::: "memory")
#define CP_WAIT2()  asm volatile("cp.async.wait_group 2;" ::: "memory")

// ---------------- K0: unfold -> fp16 plane ----------------
__global__ __launch_bounds__(256) void unfold_h(const float* __restrict__ x,
    __half* __restrict__ t)
{
    long long pidx = (long long)blockIdx.x * 256 + threadIdx.x;
    const long long NP = (long long)L_TOTAL * (DDIM / 2);
    if (pidx >= NP) return;
    int dp = (int)(pidx % (DDIM / 2));
    int l  = (int)(pidx / (DDIM / 2));
    int d0 = dp * 2;
    int b = l / HW, p = l % HW;
    int h = p / WDIM, w = p % WDIM;
    float v[2];
    #pragma unroll
    for (int j = 0; j < 2; j++) {
        int d = d0 + j;
        int c = d / 9, r = d % 9;
        int hh = h + r / 3 - 1, ww = w + r % 3 - 1;
        float vv = 0.f;
        if (hh >= 0 && hh < HDIM && ww >= 0 && ww < WDIM)
            vv = x[((b * CDIM + c) * HDIM + hh) * WDIM + ww];
        v[j] = vv;
    }
    __half2 h2; h2.x = __float2half(v[0]); h2.y = __float2half(v[1]);
    *(__half2*)(t + (size_t)l * DDIM + d0) = h2;
}

// ---------------- weight transpose: W[K,N] -> hi/lo planes [N,K] ----------------
__global__ __launch_bounds__(256) void wtrans_h(const float* __restrict__ W,
    __half* __restrict__ ohi, __half* __restrict__ olo, int K, int N)
{
    int t = blockIdx.x * 256 + threadIdx.x;
    int NP = N * (K / 2);
    if (t >= NP) return;
    int kp = t % (K / 2), n = t / (K / 2);
    int k0 = kp * 2;
    float v0 = W[(size_t)k0 * N + n];
    float v1 = W[(size_t)(k0 + 1) * N + n];
    __half2 h2, l2;
    h2.x = __float2half(v0); l2.x = __float2half(v0 - __half2float(h2.x));
    h2.y = __float2half(v1); l2.y = __float2half(v1 - __half2float(h2.y));
    size_t o = (size_t)n * K + k0;
    *(__half2*)(ohi + o) = h2;
    *(__half2*)(olo + o) = l2;
}

// ---------------- pipelined fp16 mma.sync GEMM (weight-compensated) ----------------
// C = epi(A @ (Wh+Wl)^T + bias); A [M,K] fp16, Wh/Wl [N,K] fp16.
// BM=128 BN=128 BK=32, 256 threads, 3-stage cp.async.
// MODE 1: relu -> fp16   MODE 2: sigmoid * X -> fp16   MODE 3: fp32 + bias
#define STAGE_B 24576            // 3 planes x (128 rows x 64B)
#define NSTAGE  3
#define SMEM_BYTES (NSTAGE * STAGE_B)

template<int MODE>
__global__ __launch_bounds__(256, 2) void gemm_mma(
    const __half* __restrict__ A,
    const __half* __restrict__ Bh, const __half* __restrict__ Bl,
    const float* __restrict__ bias,
    const __half* __restrict__ X,
    __half* __restrict__ Oh, float* __restrict__ Of,
    int M, int N, int Kd)
{
    extern __shared__ __align__(128) char smem[];
    const uint32_t sb = smem_u32(smem);

    const int tid  = threadIdx.x;
    const int lane = tid & 31;
    const int wid  = tid >> 5;
    const int warp_m = wid & 3;
    const int warp_n = wid >> 2;
    const int m0 = blockIdx.y * 128;
    const int n0 = blockIdx.x * 128;

    const int lr = tid >> 2;          // 0..63
    const int lc = tid & 3;           // 16B chunk 0..3

    float acc[2][8][4];
    #pragma unroll
    for (int a = 0; a < 2; a++)
        #pragma unroll
        for (int b = 0; b < 8; b++)
            #pragma unroll
            for (int c = 0; c < 4; c++) acc[a][b][c] = 0.f;

    // ldmatrix per-lane addressing (64B rows, chunk swizzle c ^ ((r>>1)&3))
    const int grp = lane >> 3, r8 = lane & 7;
    const int rowoff = ((grp & 1) << 3) + r8;
    const int cg = grp >> 1;
    int offA[2], swA[2], offB[4], swB[4];
    #pragma unroll
    for (int tm = 0; tm < 2; tm++) {
        int r = warp_m * 32 + tm * 16 + rowoff;
        offA[tm] = r * 64; swA[tm] = (r >> 1) & 3;
    }
    #pragma unroll
    for (int p = 0; p < 4; p++) {
        int r = warp_n * 64 + p * 16 + rowoff;
        offB[p] = r * 64; swB[p] = (r >> 1) & 3;
    }

    const int NIT = Kd >> 5;

    auto load_stage = [&](int st, int k0) {
        uint32_t stb = sb + st * STAGE_B;
        #pragma unroll
        for (int i = 0; i < 6; i++) {
            int plane = i >> 1;
            int r = ((i & 1) << 6) + lr;
            uint32_t dst = stb + plane * 8192 + r * 64 + ((lc ^ ((r >> 1) & 3)) << 4);
            const char* src;
            if (plane == 0)      src = (const char*)(A  + (size_t)(m0 + r) * Kd + k0 + lc * 8);
            else if (plane == 1) src = (const char*)(Bh + (size_t)(n0 + r) * Kd + k0 + lc * 8);
            else                 src = (const char*)(Bl + (size_t)(n0 + r) * Kd + k0 + lc * 8);
            cp_async16(dst, src);
        }
    };

    #pragma unroll
    for (int s = 0; s < NSTAGE; s++) {
        load_stage(s, s * 32);
        CP_COMMIT();
    }

    for (int it = 0; it < NIT; it++) {
        CP_WAIT2();
        __syncthreads();
        const int st = it % NSTAGE;
        const uint32_t stb = sb + st * STAGE_B;

        #pragma unroll
        for (int ks = 0; ks < 2; ks++) {
            uint32_t ah[2][4], bh[4][4], bl[4][4];
            #pragma unroll
            for (int tm = 0; tm < 2; tm++) {
                uint32_t colA = (uint32_t)((((ks << 1) | cg) ^ swA[tm]) << 4);
                ldm_x4(ah[tm], stb + 0 * 8192 + offA[tm] + colA);
            }
            #pragma unroll
            for (int p = 0; p < 4; p++) {
                uint32_t colB = (uint32_t)((((ks << 1) | cg) ^ swB[p]) << 4);
                ldm_x4(bh[p], stb + 1 * 8192 + offB[p] + colB);
                ldm_x4(bl[p], stb + 2 * 8192 + offB[p] + colB);
            }
            #pragma unroll
            for (int tm = 0; tm < 2; tm++)
                #pragma unroll
                for (int tn = 0; tn < 8; tn++) {
                    int p = tn >> 1, o = tn & 1;
                    mma16816(acc[tm][tn], ah[tm], bh[p][o], bh[p][2 + o]);
                    mma16816(acc[tm][tn], ah[tm], bl[p][o], bl[p][2 + o]);
                }
        }
        __syncthreads();

        int nxt = it + NSTAGE;
        if (nxt < NIT) load_stage(st, nxt * 32);
        CP_COMMIT();
    }

    // ---------------- epilogue ----------------
    const int qr = lane >> 2;
    const int qc = (lane & 3) * 2;
    #pragma unroll
    for (int tm = 0; tm < 2; tm++) {
        int mb = m0 + warp_m * 32 + tm * 16;
        #pragma unroll
        for (int tn = 0; tn < 8; tn++) {
            int n = n0 + warp_n * 64 + tn * 8 + qc;
            float bx = bias[n], by = bias[n + 1];
            #pragma unroll
            for (int half = 0; half < 2; half++) {
                int m = mb + qr + half * 8;
                float vx = acc[tm][tn][half * 2 + 0] + bx;
                float vy = acc[tm][tn][half * 2 + 1] + by;
                size_t o = (size_t)m * N + n;
                if (MODE == 1) {
                    __half2 w;
                    w.x = __float2half(fmaxf(vx, 0.f));
                    w.y = __float2half(fmaxf(vy, 0.f));
                    *(__half2*)(Oh + o) = w;
                } else if (MODE == 2) {
                    float sx = 1.f / (1.f + __expf(-vx));
                    float sy = 1.f / (1.f + __expf(-vy));
                    __half2 tv = *(const __half2*)(X + o);
                    __half2 w;
                    w.x = __float2half(__half2float(tv.x) * sx);
                    w.y = __float2half(__half2float(tv.y) * sy);
                    *(__half2*)(Oh + o) = w;
                } else {
                    float2 w; w.x = vx; w.y = vy;
                    *(float2*)(Of + o) = w;
                }
            }
        }
    }
}

// ---------------- host launch ----------------
extern "C" void kernel_launch(void* const* d_in, const int* in_sizes, int n_in,
                              void* d_out, int out_size)
{
    const float* x  = (const float*)d_in[0];
    const float* W1 = (const float*)d_in[1];
    const float* b1 = (const float*)d_in[2];
    const float* W2 = (const float*)d_in[3];
    const float* b2 = (const float*)d_in[4];
    const float* W3 = (const float*)d_in[5];
    const float* b3 = (const float*)d_in[6];
    float* out = (float*)d_out;

    __half *pt, *ph, *pp, *w1h, *w1l, *w2h, *w2l, *w3h, *w3l;
    cudaGetSymbolAddress((void**)&pt,  g_t);
    cudaGetSymbolAddress((void**)&ph,  g_h);
    cudaGetSymbolAddress((void**)&pp,  g_p);
    cudaGetSymbolAddress((void**)&w1h, g_w1h);
    cudaGetSymbolAddress((void**)&w1l, g_w1l);
    cudaGetSymbolAddress((void**)&w2h, g_w2h);
    cudaGetSymbolAddress((void**)&w2l, g_w2l);
    cudaGetSymbolAddress((void**)&w3h, g_w3h);
    cudaGetSymbolAddress((void**)&w3l, g_w3l);

    cudaFuncSetAttribute(gemm_mma<1>, cudaFuncAttributeMaxDynamicSharedMemorySize, SMEM_BYTES);
    cudaFuncSetAttribute(gemm_mma<2>, cudaFuncAttributeMaxDynamicSharedMemorySize, SMEM_BYTES);
    cudaFuncSetAttribute(gemm_mma<3>, cudaFuncAttributeMaxDynamicSharedMemorySize, SMEM_BYTES);

    long long np = (long long)L_TOTAL * (DDIM / 2);
    unfold_h<<<(unsigned)((np + 255) / 256), 256>>>(x, pt);
    wtrans_h<<<(CDIM * (DDIM / 2) + 255) / 256, 256>>>(W1, w1h, w1l, DDIM, CDIM);
    wtrans_h<<<(DDIM * (CDIM / 2) + 255) / 256, 256>>>(W2, w2h, w2l, CDIM, DDIM);
    wtrans_h<<<(CDIM * (DDIM / 2) + 255) / 256, 256>>>(W3, w3h, w3l, DDIM, CDIM);

    // K1: h = relu(t @ W1 + b1)        [25088 x 256],  K=2304
    gemm_mma<1><<<dim3(CDIM / 128, L_TOTAL / 128), 256, SMEM_BYTES>>>(
        pt, w1h, w1l, b1, nullptr, ph, nullptr, L_TOTAL, CDIM, DDIM);
    // K2: p = t * sigmoid(h @ W2 + b2) [25088 x 2304], K=256
    gemm_mma<2><<<dim3(DDIM / 128, L_TOTAL / 128), 256, SMEM_BYTES>>>(
        ph, w2h, w2l, b2, pt, pp, nullptr, L_TOTAL, DDIM, CDIM);
    // K3: out = p @ W3 + b3            [25088 x 256],  K=2304
    gemm_mma<3><<<dim3(CDIM / 128, L_TOTAL / 128), 256, SMEM_BYTES>>>(
        pp, w3h, w3l, b3, nullptr, nullptr, out, L_TOTAL, CDIM, DDIM);
}

// round 8
// speedup vs baseline: 4.6440x; 1.3922x over previous
#include <cuda_runtime.h>
#include <cuda_fp16.h>
#include <stdint.h>
#include <math.h>

// ---------------- problem constants ----------------
#define CDIM    256
#define HDIM    56
#define WDIM    56
#define HW      3136
#define L_TOTAL 25088
#define DDIM    2304

// ---------------- scratch: single fp16 planes ----------------
__device__ __align__(128) __half g_t [(size_t)L_TOTAL * DDIM];
__device__ __align__(128) __half g_h [(size_t)L_TOTAL * CDIM];
__device__ __align__(128) __half g_p [(size_t)L_TOTAL * DDIM];
__device__ __align__(128) __half g_w1[(size_t)CDIM * DDIM];
__device__ __align__(128) __half g_w2[(size_t)DDIM * CDIM];
__device__ __align__(128) __half g_w3[(size_t)CDIM * DDIM];

// ---------------- helpers ----------------
__device__ __forceinline__ uint32_t smem_u32(const void* p) {
    uint32_t a;
    asm("{ .reg .u64 t; cvta.to.shared.u64 t, %1; cvt.u32.u64 %0, t; }" : "=r"(a) : "l"(p));
    return a;
}
__device__ __forceinline__ void ldm_x4(uint32_t* r, uint32_t addr) {
    asm volatile("ldmatrix.sync.aligned.m8n8.x4.shared.b16 {%0,%1,%2,%3}, [%4];"
        : "=r"(r[0]), "=r"(r[1]), "=r"(r[2]), "=r"(r[3]) : "r"(addr));
}
__device__ __forceinline__ void mma16816(float* d, const uint32_t* a, uint32_t b0, uint32_t b1) {
    asm volatile("mma.sync.aligned.m16n8k16.row.col.f32.f16.f16.f32 "
        "{%0,%1,%2,%3}, {%4,%5,%6,%7}, {%8,%9}, {%0,%1,%2,%3};"
        : "+f"(d[0]), "+f"(d[1]), "+f"(d[2]), "+f"(d[3])
        : "r"(a[0]), "r"(a[1]), "r"(a[2]), "r"(a[3]), "r"(b0), "r"(b1));
}
__device__ __forceinline__ void cp_async16(uint32_t dst, const void* src) {
    asm volatile("cp.async.cg.shared.global [%0], [%1], 16;" :: "r"(dst), "l"(src));
}
#define CP_COMMIT() asm volatile("cp.async.commit_group;" ::: "memory")
#define CP_WAIT2()  asm volatile("cp.async.wait_group 2;" ::: "memory")

// ---------------- K0: unfold -> fp16 plane ----------------
__global__ __launch_bounds__(256) void unfold_h(const float* __restrict__ x,
    __half* __restrict__ t)
{
    long long pidx = (long long)blockIdx.x * 256 + threadIdx.x;
    const long long NP = (long long)L_TOTAL * (DDIM / 2);
    if (pidx >= NP) return;
    int dp = (int)(pidx % (DDIM / 2));
    int l  = (int)(pidx / (DDIM / 2));
    int d0 = dp * 2;
    int b = l / HW, p = l % HW;
    int h = p / WDIM, w = p % WDIM;
    float v[2];
    #pragma unroll
    for (int j = 0; j < 2; j++) {
        int d = d0 + j;
        int c = d / 9, r = d % 9;
        int hh = h + r / 3 - 1, ww = w + r % 3 - 1;
        float vv = 0.f;
        if (hh >= 0 && hh < HDIM && ww >= 0 && ww < WDIM)
            vv = x[((b * CDIM + c) * HDIM + hh) * WDIM + ww];
        v[j] = vv;
    }
    __half2 h2; h2.x = __float2half(v[0]); h2.y = __float2half(v[1]);
    *(__half2*)(t + (size_t)l * DDIM + d0) = h2;
}

// ---------------- weight transpose: W[K,N] -> fp16 [N,K] ----------------
__global__ __launch_bounds__(256) void wtrans_h(const float* __restrict__ W,
    __half* __restrict__ o, int K, int N)
{
    int t = blockIdx.x * 256 + threadIdx.x;
    int NP = N * (K / 2);
    if (t >= NP) return;
    int kp = t % (K / 2), n = t / (K / 2);
    int k0 = kp * 2;
    __half2 h2;
    h2.x = __float2half(W[(size_t)k0 * N + n]);
    h2.y = __float2half(W[(size_t)(k0 + 1) * N + n]);
    *(__half2*)(o + (size_t)n * K + k0) = h2;
}

// ---------------- pipelined fp16 mma.sync GEMM ----------------
// C = epi(A @ B^T + bias); A [M,K] fp16, B [N,K] fp16.
// BM=128 BN=128 BK=32, 256 threads, 3-stage cp.async pipeline.
// MODE 1: relu -> fp16   MODE 2: sigmoid * X -> fp16   MODE 3: fp32 + bias
#define STAGE_B 16384            // 2 planes x (128 rows x 64B)
#define NSTAGE  3
#define SMEM_BYTES (NSTAGE * STAGE_B)

template<int MODE>
__global__ __launch_bounds__(256, 2) void gemm_mma(
    const __half* __restrict__ A, const __half* __restrict__ B,
    const float* __restrict__ bias,
    const __half* __restrict__ X,
    __half* __restrict__ Oh, float* __restrict__ Of,
    int M, int N, int Kd)
{
    extern __shared__ __align__(128) char smem[];
    const uint32_t sb = smem_u32(smem);

    const int tid  = threadIdx.x;
    const int lane = tid & 31;
    const int wid  = tid >> 5;
    const int warp_m = wid & 3;
    const int warp_n = wid >> 2;
    const int m0 = blockIdx.y * 128;
    const int n0 = blockIdx.x * 128;

    const int lr = tid >> 2;          // 0..63
    const int lc = tid & 3;           // 16B chunk 0..3

    float acc[2][8][4];
    #pragma unroll
    for (int a = 0; a < 2; a++)
        #pragma unroll
        for (int b = 0; b < 8; b++)
            #pragma unroll
            for (int c = 0; c < 4; c++) acc[a][b][c] = 0.f;

    // ldmatrix per-lane addressing (64B rows, chunk swizzle c ^ ((r>>1)&3))
    const int grp = lane >> 3, r8 = lane & 7;
    const int rowoff = ((grp & 1) << 3) + r8;
    const int cg = grp >> 1;
    int offA[2], swA[2], offB[4], swB[4];
    #pragma unroll
    for (int tm = 0; tm < 2; tm++) {
        int r = warp_m * 32 + tm * 16 + rowoff;
        offA[tm] = r * 64; swA[tm] = (r >> 1) & 3;
    }
    #pragma unroll
    for (int p = 0; p < 4; p++) {
        int r = warp_n * 64 + p * 16 + rowoff;
        offB[p] = r * 64; swB[p] = (r >> 1) & 3;
    }

    const int NIT = Kd >> 5;

    auto load_stage = [&](int st, int k0) {
        uint32_t stb = sb + st * STAGE_B;
        #pragma unroll
        for (int i = 0; i < 4; i++) {
            int plane = i >> 1;
            int r = ((i & 1) << 6) + lr;
            uint32_t dst = stb + plane * 8192 + r * 64 + ((lc ^ ((r >> 1) & 3)) << 4);
            const char* src = (plane == 0)
                ? (const char*)(A + (size_t)(m0 + r) * Kd + k0 + lc * 8)
                : (const char*)(B + (size_t)(n0 + r) * Kd + k0 + lc * 8);
            cp_async16(dst, src);
        }
    };

    #pragma unroll
    for (int s = 0; s < NSTAGE; s++) {
        load_stage(s, s * 32);
        CP_COMMIT();
    }

    for (int it = 0; it < NIT; it++) {
        CP_WAIT2();
        __syncthreads();
        const int st = it % NSTAGE;
        const uint32_t stb = sb + st * STAGE_B;

        #pragma unroll
        for (int ks = 0; ks < 2; ks++) {
            uint32_t ah[2][4], bh[4][4];
            #pragma unroll
            for (int tm = 0; tm < 2; tm++) {
                uint32_t colA = (uint32_t)((((ks << 1) | cg) ^ swA[tm]) << 4);
                ldm_x4(ah[tm], stb + offA[tm] + colA);
            }
            #pragma unroll
            for (int p = 0; p < 4; p++) {
                uint32_t colB = (uint32_t)((((ks << 1) | cg) ^ swB[p]) << 4);
                ldm_x4(bh[p], stb + 8192 + offB[p] + colB);
            }
            #pragma unroll
            for (int tm = 0; tm < 2; tm++)
                #pragma unroll
                for (int tn = 0; tn < 8; tn++) {
                    int p = tn >> 1, o = tn & 1;
                    mma16816(acc[tm][tn], ah[tm], bh[p][o], bh[p][2 + o]);
                }
        }
        __syncthreads();

        int nxt = it + NSTAGE;
        if (nxt < NIT) load_stage(st, nxt * 32);
        CP_COMMIT();
    }

    // ---------------- epilogue ----------------
    const int qr = lane >> 2;
    const int qc = (lane & 3) * 2;
    #pragma unroll
    for (int tm = 0; tm < 2; tm++) {
        int mb = m0 + warp_m * 32 + tm * 16;
        #pragma unroll
        for (int tn = 0; tn < 8; tn++) {
            int n = n0 + warp_n * 64 + tn * 8 + qc;
            float bx = bias[n], by = bias[n + 1];
            #pragma unroll
            for (int half = 0; half < 2; half++) {
                int m = mb + qr + half * 8;
                float vx = acc[tm][tn][half * 2 + 0] + bx;
                float vy = acc[tm][tn][half * 2 + 1] + by;
                size_t o = (size_t)m * N + n;
                if (MODE == 1) {
                    __half2 w;
                    w.x = __float2half(fmaxf(vx, 0.f));
                    w.y = __float2half(fmaxf(vy, 0.f));
                    *(__half2*)(Oh + o) = w;
                } else if (MODE == 2) {
                    float sx = 1.f / (1.f + __expf(-vx));
                    float sy = 1.f / (1.f + __expf(-vy));
                    __half2 tv = *(const __half2*)(X + o);
                    __half2 w;
                    w.x = __float2half(__half2float(tv.x) * sx);
                    w.y = __float2half(__half2float(tv.y) * sy);
                    *(__half2*)(Oh + o) = w;
                } else {
                    float2 w; w.x = vx; w.y = vy;
                    *(float2*)(Of + o) = w;
                }
            }
        }
    }
}

// ---------------- host launch ----------------
extern "C" void kernel_launch(void* const* d_in, const int* in_sizes, int n_in,
                              void* d_out, int out_size)
{
    const float* x  = (const float*)d_in[0];
    const float* W1 = (const float*)d_in[1];
    const float* b1 = (const float*)d_in[2];
    const float* W2 = (const float*)d_in[3];
    const float* b2 = (const float*)d_in[4];
    const float* W3 = (const float*)d_in[5];
    const float* b3 = (const float*)d_in[6];
    float* out = (float*)d_out;

    __half *pt, *ph, *pp, *w1, *w2, *w3;
    cudaGetSymbolAddress((void**)&pt, g_t);
    cudaGetSymbolAddress((void**)&ph, g_h);
    cudaGetSymbolAddress((void**)&pp, g_p);
    cudaGetSymbolAddress((void**)&w1, g_w1);
    cudaGetSymbolAddress((void**)&w2, g_w2);
    cudaGetSymbolAddress((void**)&w3, g_w3);

    cudaFuncSetAttribute(gemm_mma<1>, cudaFuncAttributeMaxDynamicSharedMemorySize, SMEM_BYTES);
    cudaFuncSetAttribute(gemm_mma<2>, cudaFuncAttributeMaxDynamicSharedMemorySize, SMEM_BYTES);
    cudaFuncSetAttribute(gemm_mma<3>, cudaFuncAttributeMaxDynamicSharedMemorySize, SMEM_BYTES);

    long long np = (long long)L_TOTAL * (DDIM / 2);
    unfold_h<<<(unsigned)((np + 255) / 256), 256>>>(x, pt);
    wtrans_h<<<(CDIM * (DDIM / 2) + 255) / 256, 256>>>(W1, w1, DDIM, CDIM);
    wtrans_h<<<(DDIM * (CDIM / 2) + 255) / 256, 256>>>(W2, w2, CDIM, DDIM);
    wtrans_h<<<(CDIM * (DDIM / 2) + 255) / 256, 256>>>(W3, w3, DDIM, CDIM);

    // K1: h = relu(t @ W1 + b1)        [25088 x 256],  K=2304
    gemm_mma<1><<<dim3(CDIM / 128, L_TOTAL / 128), 256, SMEM_BYTES>>>(
        pt, w1, b1, nullptr, ph, nullptr, L_TOTAL, CDIM, DDIM);
    // K2: p = t * sigmoid(h @ W2 + b2) [25088 x 2304], K=256
    gemm_mma<2><<<dim3(DDIM / 128, L_TOTAL / 128), 256, SMEM_BYTES>>>(
        ph, w2, b2, pt, pp, nullptr, L_TOTAL, DDIM, CDIM);
    // K3: out = p @ W3 + b3            [25088 x 256],  K=2304
    gemm_mma<3><<<dim3(CDIM / 128, L_TOTAL / 128), 256, SMEM_BYTES>>>(
        pp, w3, b3, nullptr, nullptr, out, L_TOTAL, CDIM, DDIM);
}